// round 4
// baseline (speedup 1.0000x reference)
#include <cuda_runtime.h>
#include <math.h>

// Problem dims
#define BB   2
#define CCH  16
#define HH   128
#define WW   128
#define MM   9
#define NDD  9
#define MCC  144
#define HIDN 18
#define OUTC 150
#define HWD  (HH*WW*NDD)   // 147456
#define EPSBN 1e-5f

// Scratch (device globals; no runtime allocation allowed)
__device__ float g_cv [BB*(size_t)MCC*HWD];   // cost volume  [b][mc][h][w][d]
__device__ float g_h1 [BB*(size_t)HIDN*HWD];  // hidden
__device__ float g_wei[BB*(size_t)MM*HWD];    // sigmoid attention
__device__ float g_p  [BB*MCC];               // global mean pool
__device__ float g_xg [BB*MM];                // global-branch logits
__device__ float g_w1p[6*MCC*27*6];           // conv1 w dup-packed [g][mc][tap][2*3oc]
__device__ float g_w2p[3*HIDN*27*6];          // conv2 w dup-packed [g][ci][tap][2*3oc]

typedef unsigned long long u64;

__device__ __forceinline__ void upk2(float &lo, float &hi, u64 v) {
    unsigned a, b;
    asm("mov.b64 {%0, %1}, %2;" : "=r"(a), "=r"(b) : "l"(v));
    lo = __uint_as_float(a); hi = __uint_as_float(b);
}
__device__ __forceinline__ void fma2(u64 &d, u64 a, u64 b) {
    asm("fma.rn.f32x2 %0, %1, %2, %0;" : "+l"(d) : "l"(a), "l"(b));
}
__device__ __forceinline__ u64 pk2(float lo, float hi) {
    u64 r;
    asm("mov.b64 %0, {%1, %2};" : "=l"(r) : "r"(__float_as_uint(lo)), "r"(__float_as_uint(hi)));
    return r;
}

// ---------------------------------------------------------------------------
// K1: build cost volume (flat, fully parallel).
// ---------------------------------------------------------------------------
__global__ void k_build_cv(const float* __restrict__ x) {
    unsigned idx = blockIdx.x * blockDim.x + threadIdx.x;
    if (idx >= (unsigned)(BB*MCC*HWD)) return;
    unsigned i = idx;
    int d  = i % NDD;  i /= NDD;
    int w  = i % WW;   i /= WW;
    int h  = i % HH;   i /= HH;
    int mc = i % MCC;  i /= MCC;
    int b  = i;
    int m = mc / CCH, c = mc % CCH;
    int ws = w + (d - 4) * (m - 4);
    float v = 0.f;
    if ((unsigned)ws < WW)
        v = x[(((size_t)(b*CCH + c)*HH + h)*WW + ws)*MM + m];
    g_cv[idx] = v;
}

// ---------------------------------------------------------------------------
// K2: mean pool per (b,mc). Deterministic tree reduce.
// ---------------------------------------------------------------------------
__global__ void k_reduce() {
    int bm = blockIdx.x;
    const float* src = g_cv + (size_t)bm * HWD;
    float s = 0.f;
    for (int i = threadIdx.x; i < HWD; i += 256) s += src[i];
    __shared__ float sh[256];
    sh[threadIdx.x] = s;
    __syncthreads();
    for (int o = 128; o > 0; o >>= 1) {
        if (threadIdx.x < o) sh[threadIdx.x] += sh[threadIdx.x + o];
        __syncthreads();
    }
    if (threadIdx.x == 0) g_p[bm] = sh[0] * (1.0f / HWD);
}

// ---------------------------------------------------------------------------
// K3: global attention branch (center tap only at 1x1x1 spatial).
// ---------------------------------------------------------------------------
__global__ void k_global(const float* __restrict__ w1, const float* __restrict__ b1,
                         const float* __restrict__ g1, const float* __restrict__ be1,
                         const float* __restrict__ m1, const float* __restrict__ v1,
                         const float* __restrict__ w2, const float* __restrict__ b2,
                         const float* __restrict__ g2, const float* __restrict__ be2,
                         const float* __restrict__ m2, const float* __restrict__ v2) {
    __shared__ float gh[BB*HIDN];
    int t = threadIdx.x;
    if (t < BB*HIDN) {
        int b = t / HIDN, o = t % HIDN;
        float s = b1[o];
        for (int c = 0; c < MCC; c++)
            s += w1[(o*MCC + c)*27 + 13] * g_p[b*MCC + c];
        float sc = g1[o] * rsqrtf(v1[o] + EPSBN);
        s = (s - m1[o]) * sc + be1[o];
        gh[t] = fmaxf(s, 0.f);
    }
    __syncthreads();
    if (t < BB*MM) {
        int b = t / MM, og = t % MM;
        float s = b2[og];
        for (int o = 0; o < HIDN; o++)
            s += w2[(og*HIDN + o)*27 + 13] * gh[b*HIDN + o];
        float sc = g2[og] * rsqrtf(v2[og] + EPSBN);
        g_xg[t] = (s - m2[og]) * sc + be2[og];
    }
}

// ---------------------------------------------------------------------------
// K-pack: duplicate conv weights into {w,w} pairs, 3-oc groups.
// ---------------------------------------------------------------------------
__global__ void k_packw(const float* __restrict__ w1, const float* __restrict__ w2) {
    int t = blockIdx.x * 256 + threadIdx.x;
    if (t < HIDN*MCC*27) {
        int oc = t / (MCC*27); int r = t % (MCC*27);
        int mc = r / 27, tap = r % 27;
        int g = oc / 3, o = oc % 3;
        float v = w1[((size_t)oc*MCC + mc)*27 + tap];
        float* d = &g_w1p[((size_t)(g*MCC + mc)*27 + tap)*6 + 2*o];
        d[0] = v; d[1] = v;
    }
    if (t < MM*HIDN*27) {
        int oc = t / (HIDN*27); int r = t % (HIDN*27);
        int ci = r / 27, tap = r % 27;
        int g = oc / 3, o = oc % 3;
        float v = w2[((size_t)oc*HIDN + ci)*27 + tap];
        float* d = &g_w2p[((size_t)(g*HIDN + ci)*27 + tap)*6 + 2*o];
        d[0] = v; d[1] = v;
    }
}

// ---------------------------------------------------------------------------
// K4/K5: 3x3x3 conv, 3 oc x 9 d per thread, f32x2 over d with DUAL-PARITY smem
// layout so every FMA2 operand is a direct aligned LDS.64 (no pack movs).
// Cell = 28 floats: [0..11] z-parity-E (z=d+1), [12..22] parity-O (slot 12+i
// holds value at z=i+1), rest zero pads.
// Block 128 = 16(w) x 8(h). grid z = B * NOCG (3 oc per group).
// ---------------------------------------------------------------------------
template<int CIN, int MCH, int NOCG, int OCTOT, bool FIRST>
__global__ __launch_bounds__(128, 4) void k_conv(
        const float* __restrict__ gam, const float* __restrict__ bet,
        const float* __restrict__ mu,  const float* __restrict__ var,
        const float* __restrict__ bias) {
    __shared__ float tile[MCH*10*18*28];
    __shared__ float wsh[MCH*27*6];

    const float* src = FIRST ? g_cv : g_h1;
    const float* wpk = FIRST ? g_w1p : g_w2p;
    float* dst       = FIRST ? g_h1 : g_wei;

    int tid = threadIdx.x;
    int tx = tid & 15, ty = tid >> 4;        // 16 x 8
    int gz = blockIdx.z;
    int b = gz / NOCG, g = gz % NOCG;
    int w0 = blockIdx.x * 16, h0 = blockIdx.y * 8;

    for (int i = tid; i < MCH*10*18*28; i += 128) tile[i] = 0.f;

    u64 acc[3][5];
#pragma unroll
    for (int o = 0; o < 3; o++)
#pragma unroll
        for (int p = 0; p < 5; p++) acc[o][p] = 0ull;

    const float* srcb = src + (size_t)b*CIN*HWD;
    const float* wg   = wpk + (size_t)g*CIN*27*6;

    for (int c0 = 0; c0 < CIN; c0 += MCH) {
        __syncthreads();
        for (int i = tid; i < MCH*27*6; i += 128)
            wsh[i] = wg[(size_t)c0*27*6 + i];
        for (int i = tid; i < MCH*10*18*9; i += 128) {
            int d = i % 9; int r = i / 9;
            int wi = r % 18; r /= 18;
            int hi = r % 10; int mcl = r / 10;
            int h = h0 - 1 + hi, w = w0 - 1 + wi;
            float v = 0.f;
            if ((unsigned)h < HH && (unsigned)w < WW)
                v = srcb[(size_t)(c0 + mcl)*HWD + (h*WW + w)*9 + d];
            int base = ((mcl*10 + hi)*18 + wi)*28;
            tile[base + d + 1]  = v;   // E parity: z = d+1
            tile[base + 12 + d] = v;   // O parity: slot 12+(z-1)
        }
        __syncthreads();
#pragma unroll 1
        for (int mcl = 0; mcl < MCH; mcl++) {
            const float* tb = tile + mcl*10*18*28;
            const u64*   wb = (const u64*)(wsh + mcl*27*6);
#pragma unroll
            for (int k0 = 0; k0 < 3; k0++)
#pragma unroll
            for (int k1 = 0; k1 < 3; k1++) {
                const u64* cp = (const u64*)(tb + ((ty + k0)*18 + (tx + k1))*28);
                u64 E0 = cp[0], E1 = cp[1], E2 = cp[2], E3 = cp[3], E4 = cp[4], E5 = cp[5];
                u64 O0 = cp[6], O1 = cp[7], O2 = cp[8], O3 = cp[9], O4 = cp[10];
                const u64* wr = wb + (k0*3 + k1)*9;   // 3 k2 x 3 oc (u64 each)
#pragma unroll
                for (int o = 0; o < 3; o++) {         // k2 = 0 : E[p]
                    u64 wv = wr[o];
                    fma2(acc[o][0], wv, E0); fma2(acc[o][1], wv, E1);
                    fma2(acc[o][2], wv, E2); fma2(acc[o][3], wv, E3);
                    fma2(acc[o][4], wv, E4);
                }
#pragma unroll
                for (int o = 0; o < 3; o++) {         // k2 = 1 : O[p]
                    u64 wv = wr[3 + o];
                    fma2(acc[o][0], wv, O0); fma2(acc[o][1], wv, O1);
                    fma2(acc[o][2], wv, O2); fma2(acc[o][3], wv, O3);
                    fma2(acc[o][4], wv, O4);
                }
#pragma unroll
                for (int o = 0; o < 3; o++) {         // k2 = 2 : E[p+1]
                    u64 wv = wr[6 + o];
                    fma2(acc[o][0], wv, E1); fma2(acc[o][1], wv, E2);
                    fma2(acc[o][2], wv, E3); fma2(acc[o][3], wv, E4);
                    fma2(acc[o][4], wv, E5);
                }
            }
        }
    }

    int h = h0 + ty, w = w0 + tx;
#pragma unroll
    for (int o = 0; o < 3; o++) {
        int oc = g*3 + o;
        float s  = gam[oc] * rsqrtf(var[oc] + EPSBN);
        float bi = (bias[oc] - mu[oc]) * s + bet[oc];
        float xg = FIRST ? 0.f : g_xg[b*MM + oc];
        float* dp = dst + (size_t)(b*OCTOT + oc)*HWD + (h*WW + w)*9;
#pragma unroll
        for (int p = 0; p < 5; p++) {
            float lo, hi;
            upk2(lo, hi, acc[o][p]);
            float y0 = lo*s + bi;
            if (FIRST) y0 = fmaxf(y0, 0.f);
            else       y0 = 1.f / (1.f + expf(-(y0 + xg)));
            dp[2*p] = y0;
            if (p < 4) {
                float y1 = hi*s + bi;
                if (FIRST) y1 = fmaxf(y1, 0.f);
                else       y1 = 1.f / (1.f + expf(-(y1 + xg)));
                dp[2*p + 1] = y1;
            }
        }
    }
}

// ---------------------------------------------------------------------------
// K6: conv_last GEMM with f32x2 (round-2 measured-best version).
// A[k,p] = wei * cv staged in smem; thread: 10 oc-pairs x 4 p.
// ---------------------------------------------------------------------------
extern __shared__ float sfin[];
__global__ __launch_bounds__(256) void k_final(
        const float* __restrict__ clw, const float* __restrict__ clb,
        float* __restrict__ out) {
    float* As = sfin;               // [144][128]
    float* Ws = sfin + 144*128;     // [144][162] (oc >= 150 zero)
    int b  = blockIdx.y;
    int p0 = blockIdx.x * 128;
    int tid = threadIdx.x;

    for (int t = tid; t < 162*144; t += 256) {
        int oc = t / 144, k = t % 144;        // k-coalesced LDG
        Ws[k*162 + oc] = (oc < OUTC) ? clw[oc*MCC + k] : 0.f;
    }
    const float* cvb = g_cv  + (size_t)b*MCC*HWD + p0;
    const float* wb  = g_wei + (size_t)b*MM *HWD + p0;
    for (int t = tid; t < 144*128; t += 256) {
        int k = t >> 7, p = t & 127;
        As[t] = cvb[(size_t)k*HWD + p] * wb[(size_t)(k >> 4)*HWD + p];
    }
    __syncthreads();

    int tx = tid & 31, ty = tid >> 5;
    u64 acc[10][4];
#pragma unroll
    for (int j = 0; j < 10; j++)
#pragma unroll
        for (int i = 0; i < 4; i++) acc[j][i] = 0ull;

#pragma unroll 2
    for (int k = 0; k < 144; k++) {
        float4 a = *(const float4*)(As + k*128 + tx*4);
        u64 a0 = pk2(a.x, a.x), a1 = pk2(a.y, a.y);
        u64 a2 = pk2(a.z, a.z), a3 = pk2(a.w, a.w);
        const u64* wrow = (const u64*)(Ws + k*162) + ty*10;
#pragma unroll
        for (int j = 0; j < 10; j++) {
            u64 wv = wrow[j];
            fma2(acc[j][0], wv, a0); fma2(acc[j][1], wv, a1);
            fma2(acc[j][2], wv, a2); fma2(acc[j][3], wv, a3);
        }
    }

#pragma unroll
    for (int j = 0; j < 10; j++) {
        int oc0 = ty*20 + 2*j;
        float lo[4], hi[4];
#pragma unroll
        for (int i = 0; i < 4; i++) upk2(lo[i], hi[i], acc[j][i]);
        if (oc0 < OUTC) {
            float bv = clb[oc0];
            float4 r = make_float4(lo[0]+bv, lo[1]+bv, lo[2]+bv, lo[3]+bv);
            *(float4*)(out + (size_t)(b*OUTC + oc0)*HWD + p0 + tx*4) = r;
        }
        if (oc0 + 1 < OUTC) {
            float bv = clb[oc0+1];
            float4 r = make_float4(hi[0]+bv, hi[1]+bv, hi[2]+bv, hi[3]+bv);
            *(float4*)(out + (size_t)(b*OUTC + oc0 + 1)*HWD + p0 + tx*4) = r;
        }
    }
}

// ---------------------------------------------------------------------------
extern "C" void kernel_launch(void* const* d_in, const int* in_sizes, int n_in,
                              void* d_out, int out_size) {
    const float* x      = (const float*)d_in[0];
    const float* la_w1  = (const float*)d_in[1];
    const float* la_b1  = (const float*)d_in[2];
    const float* la_g1  = (const float*)d_in[3];
    const float* la_be1 = (const float*)d_in[4];
    const float* la_m1  = (const float*)d_in[5];
    const float* la_v1  = (const float*)d_in[6];
    const float* la_w2  = (const float*)d_in[7];
    const float* la_b2  = (const float*)d_in[8];
    const float* la_g2  = (const float*)d_in[9];
    const float* la_be2 = (const float*)d_in[10];
    const float* la_m2  = (const float*)d_in[11];
    const float* la_v2  = (const float*)d_in[12];
    const float* ga_w1  = (const float*)d_in[13];
    const float* ga_b1  = (const float*)d_in[14];
    const float* ga_g1  = (const float*)d_in[15];
    const float* ga_be1 = (const float*)d_in[16];
    const float* ga_m1  = (const float*)d_in[17];
    const float* ga_v1  = (const float*)d_in[18];
    const float* ga_w2  = (const float*)d_in[19];
    const float* ga_b2  = (const float*)d_in[20];
    const float* ga_g2  = (const float*)d_in[21];
    const float* ga_be2 = (const float*)d_in[22];
    const float* ga_m2  = (const float*)d_in[23];
    const float* ga_v2  = (const float*)d_in[24];
    const float* cl_w   = (const float*)d_in[25];
    const float* cl_b   = (const float*)d_in[26];
    float* out = (float*)d_out;

    unsigned ncv = BB*MCC*HWD;
    k_build_cv<<<(ncv + 255)/256, 256>>>(x);
    k_reduce<<<BB*MCC, 256>>>();
    k_global<<<1, 64>>>(ga_w1, ga_b1, ga_g1, ga_be1, ga_m1, ga_v1,
                        ga_w2, ga_b2, ga_g2, ga_be2, ga_m2, ga_v2);
    k_packw<<<(HIDN*MCC*27 + 255)/256, 256>>>(la_w1, la_w2);

    dim3 g1(WW/16, HH/8, BB*6);
    k_conv<MCC, 2, 6, 18, true><<<g1, 128>>>(la_g1, la_be1, la_m1, la_v1, la_b1);
    dim3 g2(WW/16, HH/8, BB*3);
    k_conv<HIDN, 2, 3, 9, false><<<g2, 128>>>(la_g2, la_be2, la_m2, la_v2, la_b2);

    const int smem_fin = (144*128 + 144*162) * 4;   // 167040
    cudaFuncSetAttribute(k_final, cudaFuncAttributeMaxDynamicSharedMemorySize, smem_fin);
    dim3 gf(HWD/128, BB);
    k_final<<<gf, 256, smem_fin>>>(cl_w, cl_b, out);
}

// round 5
// speedup vs baseline: 1.0707x; 1.0707x over previous
#include <cuda_runtime.h>
#include <math.h>

// Problem dims
#define BB   2
#define CCH  16
#define HH   128
#define WW   128
#define MM   9
#define NDD  9
#define MCC  144
#define HIDN 18
#define OUTC 150
#define HWD  (HH*WW*NDD)   // 147456
#define EPSBN 1e-5f

// Scratch (device globals; no runtime allocation allowed)
__device__ float g_cv [BB*(size_t)MCC*HWD];   // cost volume  [b][mc][h][w][d]
__device__ float g_h1 [BB*(size_t)HIDN*HWD];  // hidden
__device__ float g_wei[BB*(size_t)MM*HWD];    // sigmoid attention
__device__ float g_p  [BB*MCC];               // global mean pool
__device__ float g_xg [BB*MM];                // global-branch logits
// conv weights channel-pair packed: [g][cpair][(k0*3+k1)*9 + k2*3 + o] -> u64 {w_c0, w_c1}
__device__ float g_w1p[6*72*81*2];            // conv1: 6 ocg x 72 cpairs
__device__ float g_w2p[3*9*81*2];             // conv2: 3 ocg x 9 cpairs

typedef unsigned long long u64;

__device__ __forceinline__ void upk2(float &lo, float &hi, u64 v) {
    unsigned a, b;
    asm("mov.b64 {%0, %1}, %2;" : "=r"(a), "=r"(b) : "l"(v));
    lo = __uint_as_float(a); hi = __uint_as_float(b);
}
__device__ __forceinline__ void fma2(u64 &d, u64 a, u64 b) {
    asm("fma.rn.f32x2 %0, %1, %2, %0;" : "+l"(d) : "l"(a), "l"(b));
}
__device__ __forceinline__ u64 pk2(float lo, float hi) {
    u64 r;
    asm("mov.b64 %0, {%1, %2};" : "=l"(r) : "r"(__float_as_uint(lo)), "r"(__float_as_uint(hi)));
    return r;
}

// ---------------------------------------------------------------------------
// K1: build cost volume (flat, fully parallel).
// ---------------------------------------------------------------------------
__global__ void k_build_cv(const float* __restrict__ x) {
    unsigned idx = blockIdx.x * blockDim.x + threadIdx.x;
    if (idx >= (unsigned)(BB*MCC*HWD)) return;
    unsigned i = idx;
    int d  = i % NDD;  i /= NDD;
    int w  = i % WW;   i /= WW;
    int h  = i % HH;   i /= HH;
    int mc = i % MCC;  i /= MCC;
    int b  = i;
    int m = mc / CCH, c = mc % CCH;
    int ws = w + (d - 4) * (m - 4);
    float v = 0.f;
    if ((unsigned)ws < WW)
        v = x[(((size_t)(b*CCH + c)*HH + h)*WW + ws)*MM + m];
    g_cv[idx] = v;
}

// ---------------------------------------------------------------------------
// K2: mean pool per (b,mc). Deterministic tree reduce.
// ---------------------------------------------------------------------------
__global__ void k_reduce() {
    int bm = blockIdx.x;
    const float* src = g_cv + (size_t)bm * HWD;
    float s = 0.f;
    for (int i = threadIdx.x; i < HWD; i += 256) s += src[i];
    __shared__ float sh[256];
    sh[threadIdx.x] = s;
    __syncthreads();
    for (int o = 128; o > 0; o >>= 1) {
        if (threadIdx.x < o) sh[threadIdx.x] += sh[threadIdx.x + o];
        __syncthreads();
    }
    if (threadIdx.x == 0) g_p[bm] = sh[0] * (1.0f / HWD);
}

// ---------------------------------------------------------------------------
// K3: global attention branch (center tap only at 1x1x1 spatial).
// ---------------------------------------------------------------------------
__global__ void k_global(const float* __restrict__ w1, const float* __restrict__ b1,
                         const float* __restrict__ g1, const float* __restrict__ be1,
                         const float* __restrict__ m1, const float* __restrict__ v1,
                         const float* __restrict__ w2, const float* __restrict__ b2,
                         const float* __restrict__ g2, const float* __restrict__ be2,
                         const float* __restrict__ m2, const float* __restrict__ v2) {
    __shared__ float gh[BB*HIDN];
    int t = threadIdx.x;
    if (t < BB*HIDN) {
        int b = t / HIDN, o = t % HIDN;
        float s = b1[o];
        for (int c = 0; c < MCC; c++)
            s += w1[(o*MCC + c)*27 + 13] * g_p[b*MCC + c];
        float sc = g1[o] * rsqrtf(v1[o] + EPSBN);
        s = (s - m1[o]) * sc + be1[o];
        gh[t] = fmaxf(s, 0.f);
    }
    __syncthreads();
    if (t < BB*MM) {
        int b = t / MM, og = t % MM;
        float s = b2[og];
        for (int o = 0; o < HIDN; o++)
            s += w2[(og*HIDN + o)*27 + 13] * gh[b*HIDN + o];
        float sc = g2[og] * rsqrtf(v2[og] + EPSBN);
        g_xg[t] = (s - m2[og]) * sc + be2[og];
    }
}

// ---------------------------------------------------------------------------
// K-pack: channel-pair interleave conv weights.
// source: w[oc][cin][k0][k1][k2]; dest u64 index (k0*3+k1)*9 + k2*3 + (oc%3)
// within [g=oc/3][cpair=cin/2]; parity = cin&1.
// ---------------------------------------------------------------------------
__global__ void k_packw(const float* __restrict__ w1, const float* __restrict__ w2) {
    int t = blockIdx.x * 256 + threadIdx.x;
    if (t < HIDN*MCC*27) {
        int tap = t % 27; int r = t / 27;
        int ch = r % MCC; int oc = r / MCC;
        int k0 = tap / 9, k1 = (tap / 3) % 3, k2 = tap % 3;
        int g = oc / 3, o = oc % 3;
        int cp = ch >> 1, par = ch & 1;
        float v = w1[((size_t)oc*MCC + ch)*27 + tap];
        g_w1p[(((size_t)(g*72 + cp)*81) + (k0*3 + k1)*9 + k2*3 + o)*2 + par] = v;
    }
    if (t < MM*HIDN*27) {
        int tap = t % 27; int r = t / 27;
        int ch = r % HIDN; int oc = r / HIDN;
        int k0 = tap / 9, k1 = (tap / 3) % 3, k2 = tap % 3;
        int g = oc / 3, o = oc % 3;
        int cp = ch >> 1, par = ch & 1;
        float v = w2[((size_t)oc*HIDN + ch)*27 + tap];
        g_w2p[(((size_t)(g*9 + cp)*81) + (k0*3 + k1)*9 + k2*3 + o)*2 + par] = v;
    }
}

// ---------------------------------------------------------------------------
// K4/K5: 3x3x3 conv, f32x2 paired over INPUT-CHANNEL parity.
// Thread: one (h,w), 3 oc, 9 d. acc[o][d] = u64 channel-parity partials.
// Tile cell = 26 floats: z slots 0..10, each {c_even, c_odd}; z=d+1; halo zero.
// Per (k0,k1): 11 x-LDS.64 + 9 w-LDS.64 -> 81 FMA2 (x value reused by all k2).
// Block 128 = 16(w) x 8(h). grid z = B*NOCG (3 oc per group).
// ---------------------------------------------------------------------------
template<int CPAIRS, int MCH, int NOCG, int OCTOT, bool FIRST>
__global__ __launch_bounds__(128) void k_conv(
        const float* __restrict__ gam, const float* __restrict__ bet,
        const float* __restrict__ mu,  const float* __restrict__ var,
        const float* __restrict__ bias) {
    __shared__ float tile[MCH*10*18*26];
    __shared__ float wsh[MCH*162];

    const float* src = FIRST ? g_cv : g_h1;
    const float* wpk = FIRST ? g_w1p : g_w2p;
    float* dst       = FIRST ? g_h1 : g_wei;

    int tid = threadIdx.x;
    int tx = tid & 15, ty = tid >> 4;        // 16 x 8
    int gz = blockIdx.z;
    int b = gz / NOCG, g = gz % NOCG;
    int w0 = blockIdx.x * 16, h0 = blockIdx.y * 8;

    for (int i = tid; i < MCH*10*18*26; i += 128) tile[i] = 0.f;

    u64 acc[3][9];
#pragma unroll
    for (int o = 0; o < 3; o++)
#pragma unroll
        for (int d = 0; d < 9; d++) acc[o][d] = 0ull;

    const float* srcb = src + (size_t)b*(2*CPAIRS)*HWD;
    const float* wg   = wpk + (size_t)g*CPAIRS*162;

    for (int c0 = 0; c0 < CPAIRS; c0 += MCH) {
        __syncthreads();
        for (int i = tid; i < MCH*162; i += 128)
            wsh[i] = wg[(size_t)c0*162 + i];
        // load MCH cpairs: d fastest (coalesced 9-runs), channel parity interleaved in cell
        for (int i = tid; i < MCH*2*10*18*9; i += 128) {
            int d = i % 9; int r = i / 9;
            int wi = r % 18; r /= 18;
            int hi = r % 10; r /= 10;
            int c  = r & 1;  int mcl = r >> 1;
            int h = h0 - 1 + hi, w = w0 - 1 + wi;
            float v = 0.f;
            if ((unsigned)h < HH && (unsigned)w < WW)
                v = srcb[(size_t)(2*(c0 + mcl) + c)*HWD + (h*WW + w)*9 + d];
            tile[((mcl*10 + hi)*18 + wi)*26 + 2*(d + 1) + c] = v;
        }
        __syncthreads();
#pragma unroll 1
        for (int mcl = 0; mcl < MCH; mcl++) {
            const float* tb = tile + mcl*10*18*26;
            const u64*   wb = (const u64*)(wsh + mcl*162);
#pragma unroll
            for (int k0 = 0; k0 < 3; k0++)
#pragma unroll
            for (int k1 = 0; k1 < 3; k1++) {
                const u64* cp = (const u64*)(tb + ((ty + k0)*18 + (tx + k1))*26);
                u64 X[11];
#pragma unroll
                for (int z = 0; z < 11; z++) X[z] = cp[z];
                const u64* wr = wb + (k0*3 + k1)*9;
#pragma unroll
                for (int k2 = 0; k2 < 3; k2++)
#pragma unroll
                for (int o = 0; o < 3; o++) {
                    u64 wv = wr[k2*3 + o];
#pragma unroll
                    for (int d = 0; d < 9; d++)
                        fma2(acc[o][d], wv, X[d + k2]);
                }
            }
        }
    }

    int h = h0 + ty, w = w0 + tx;
#pragma unroll
    for (int o = 0; o < 3; o++) {
        int oc = g*3 + o;
        float s  = gam[oc] * rsqrtf(var[oc] + EPSBN);
        float bi = (bias[oc] - mu[oc]) * s + bet[oc];
        float xg = FIRST ? 0.f : g_xg[b*MM + oc];
        float* dp = dst + (size_t)(b*OCTOT + oc)*HWD + (h*WW + w)*9;
#pragma unroll
        for (int d = 0; d < 9; d++) {
            float lo, hi;
            upk2(lo, hi, acc[o][d]);
            float y = (lo + hi)*s + bi;
            if (FIRST) y = fmaxf(y, 0.f);
            else       y = 1.f / (1.f + expf(-(y + xg)));
            dp[d] = y;
        }
    }
}

// ---------------------------------------------------------------------------
// K6: conv_last GEMM with f32x2 (round-2 measured-best version).
// ---------------------------------------------------------------------------
extern __shared__ float sfin[];
__global__ __launch_bounds__(256) void k_final(
        const float* __restrict__ clw, const float* __restrict__ clb,
        float* __restrict__ out) {
    float* As = sfin;               // [144][128]
    float* Ws = sfin + 144*128;     // [144][162] (oc >= 150 zero)
    int b  = blockIdx.y;
    int p0 = blockIdx.x * 128;
    int tid = threadIdx.x;

    for (int t = tid; t < 162*144; t += 256) {
        int oc = t / 144, k = t % 144;
        Ws[k*162 + oc] = (oc < OUTC) ? clw[oc*MCC + k] : 0.f;
    }
    const float* cvb = g_cv  + (size_t)b*MCC*HWD + p0;
    const float* wb  = g_wei + (size_t)b*MM *HWD + p0;
    for (int t = tid; t < 144*128; t += 256) {
        int k = t >> 7, p = t & 127;
        As[t] = cvb[(size_t)k*HWD + p] * wb[(size_t)(k >> 4)*HWD + p];
    }
    __syncthreads();

    int tx = tid & 31, ty = tid >> 5;
    u64 acc[10][4];
#pragma unroll
    for (int j = 0; j < 10; j++)
#pragma unroll
        for (int i = 0; i < 4; i++) acc[j][i] = 0ull;

#pragma unroll 2
    for (int k = 0; k < 144; k++) {
        float4 a = *(const float4*)(As + k*128 + tx*4);
        u64 a0 = pk2(a.x, a.x), a1 = pk2(a.y, a.y);
        u64 a2 = pk2(a.z, a.z), a3 = pk2(a.w, a.w);
        const u64* wrow = (const u64*)(Ws + k*162) + ty*10;
#pragma unroll
        for (int j = 0; j < 10; j++) {
            u64 wv = wrow[j];
            fma2(acc[j][0], wv, a0); fma2(acc[j][1], wv, a1);
            fma2(acc[j][2], wv, a2); fma2(acc[j][3], wv, a3);
        }
    }

#pragma unroll
    for (int j = 0; j < 10; j++) {
        int oc0 = ty*20 + 2*j;
        float lo[4], hi[4];
#pragma unroll
        for (int i = 0; i < 4; i++) upk2(lo[i], hi[i], acc[j][i]);
        if (oc0 < OUTC) {
            float bv = clb[oc0];
            float4 r = make_float4(lo[0]+bv, lo[1]+bv, lo[2]+bv, lo[3]+bv);
            *(float4*)(out + (size_t)(b*OUTC + oc0)*HWD + p0 + tx*4) = r;
        }
        if (oc0 + 1 < OUTC) {
            float bv = clb[oc0+1];
            float4 r = make_float4(hi[0]+bv, hi[1]+bv, hi[2]+bv, hi[3]+bv);
            *(float4*)(out + (size_t)(b*OUTC + oc0 + 1)*HWD + p0 + tx*4) = r;
        }
    }
}

// ---------------------------------------------------------------------------
extern "C" void kernel_launch(void* const* d_in, const int* in_sizes, int n_in,
                              void* d_out, int out_size) {
    const float* x      = (const float*)d_in[0];
    const float* la_w1  = (const float*)d_in[1];
    const float* la_b1  = (const float*)d_in[2];
    const float* la_g1  = (const float*)d_in[3];
    const float* la_be1 = (const float*)d_in[4];
    const float* la_m1  = (const float*)d_in[5];
    const float* la_v1  = (const float*)d_in[6];
    const float* la_w2  = (const float*)d_in[7];
    const float* la_b2  = (const float*)d_in[8];
    const float* la_g2  = (const float*)d_in[9];
    const float* la_be2 = (const float*)d_in[10];
    const float* la_m2  = (const float*)d_in[11];
    const float* la_v2  = (const float*)d_in[12];
    const float* ga_w1  = (const float*)d_in[13];
    const float* ga_b1  = (const float*)d_in[14];
    const float* ga_g1  = (const float*)d_in[15];
    const float* ga_be1 = (const float*)d_in[16];
    const float* ga_m1  = (const float*)d_in[17];
    const float* ga_v1  = (const float*)d_in[18];
    const float* ga_w2  = (const float*)d_in[19];
    const float* ga_b2  = (const float*)d_in[20];
    const float* ga_g2  = (const float*)d_in[21];
    const float* ga_be2 = (const float*)d_in[22];
    const float* ga_m2  = (const float*)d_in[23];
    const float* ga_v2  = (const float*)d_in[24];
    const float* cl_w   = (const float*)d_in[25];
    const float* cl_b   = (const float*)d_in[26];
    float* out = (float*)d_out;

    unsigned ncv = BB*MCC*HWD;
    k_build_cv<<<(ncv + 255)/256, 256>>>(x);
    k_reduce<<<BB*MCC, 256>>>();
    k_global<<<1, 64>>>(ga_w1, ga_b1, ga_g1, ga_be1, ga_m1, ga_v1,
                        ga_w2, ga_b2, ga_g2, ga_be2, ga_m2, ga_v2);
    k_packw<<<(HIDN*MCC*27 + 255)/256, 256>>>(la_w1, la_w2);

    // conv1: 144 ch = 72 cpairs, 6 oc-groups of 3
    dim3 g1(WW/16, HH/8, BB*6);
    k_conv<72, 2, 6, 18, true><<<g1, 128>>>(la_g1, la_be1, la_m1, la_v1, la_b1);
    // conv2: 18 ch = 9 cpairs, 3 oc-groups of 3
    dim3 g2(WW/16, HH/8, BB*3);
    k_conv<9, 1, 3, 9, false><<<g2, 128>>>(la_g2, la_be2, la_m2, la_v2, la_b2);

    const int smem_fin = (144*128 + 144*162) * 4;   // 167040
    cudaFuncSetAttribute(k_final, cudaFuncAttributeMaxDynamicSharedMemorySize, smem_fin);
    dim3 gf(HWD/128, BB);
    k_final<<<gf, 256, smem_fin>>>(cl_w, cl_b, out);
}

// round 6
// speedup vs baseline: 1.5458x; 1.4438x over previous
#include <cuda_runtime.h>
#include <math.h>

// Problem dims
#define BB   2
#define CCH  16
#define HH   128
#define WW   128
#define MM   9
#define NDD  9
#define MCC  144
#define HIDN 18
#define OUTC 150
#define HWD  (HH*WW*NDD)   // 147456
#define EPSBN 1e-5f

// Scratch (device globals; no runtime allocation allowed)
__device__ float g_cv [BB*(size_t)MCC*HWD];   // cost volume  [b][mc][h][w][d]
__device__ float g_h1 [BB*(size_t)HIDN*HWD];  // hidden
__device__ float g_wei[BB*(size_t)MM*HWD];    // sigmoid attention
__device__ float g_p  [BB*MCC];               // global mean pool
__device__ float g_xg [BB*MM];                // global-branch logits
// conv weights channel-pair packed: [g][cpair][(k0*3+k1)*9 + k2*3 + o] -> u64 {w_c0, w_c1}
__device__ float g_w1p[6*72*81*2];            // conv1: 6 ocg x 72 cpairs
__device__ float g_w2p[3*9*81*2];             // conv2: 3 ocg x 9 cpairs

typedef unsigned long long u64;

__device__ __forceinline__ void upk2(float &lo, float &hi, u64 v) {
    unsigned a, b;
    asm("mov.b64 {%0, %1}, %2;" : "=r"(a), "=r"(b) : "l"(v));
    lo = __uint_as_float(a); hi = __uint_as_float(b);
}
__device__ __forceinline__ void fma2(u64 &d, u64 a, u64 b) {
    asm("fma.rn.f32x2 %0, %1, %2, %0;" : "+l"(d) : "l"(a), "l"(b));
}
__device__ __forceinline__ u64 pk2(float lo, float hi) {
    u64 r;
    asm("mov.b64 %0, {%1, %2};" : "=l"(r) : "r"(__float_as_uint(lo)), "r"(__float_as_uint(hi)));
    return r;
}
__device__ __forceinline__ void cpa4(unsigned saddr, const void* gaddr, bool valid) {
    int sz = valid ? 4 : 0;   // src-size 0 -> zero-fill, no global read
    asm volatile("cp.async.ca.shared.global [%0], [%1], 4, %2;"
                 :: "r"(saddr), "l"(gaddr), "r"(sz));
}
__device__ __forceinline__ void cpa_commit() {
    asm volatile("cp.async.commit_group;");
}

// ---------------------------------------------------------------------------
// K-pack: channel-pair interleave conv weights.
// ---------------------------------------------------------------------------
__global__ void k_packw(const float* __restrict__ w1, const float* __restrict__ w2) {
    int t = blockIdx.x * 256 + threadIdx.x;
    if (t < HIDN*MCC*27) {
        int tap = t % 27; int r = t / 27;
        int ch = r % MCC; int oc = r / MCC;
        int k0 = tap / 9, k1 = (tap / 3) % 3, k2 = tap % 3;
        int g = oc / 3, o = oc % 3;
        int cp = ch >> 1, par = ch & 1;
        float v = w1[((size_t)oc*MCC + ch)*27 + tap];
        g_w1p[(((size_t)(g*72 + cp)*81) + (k0*3 + k1)*9 + k2*3 + o)*2 + par] = v;
    }
    if (t < MM*HIDN*27) {
        int tap = t % 27; int r = t / 27;
        int ch = r % HIDN; int oc = r / HIDN;
        int k0 = tap / 9, k1 = (tap / 3) % 3, k2 = tap % 3;
        int g = oc / 3, o = oc % 3;
        int cp = ch >> 1, par = ch & 1;
        float v = w2[((size_t)oc*HIDN + ch)*27 + tap];
        g_w2p[(((size_t)(g*9 + cp)*81) + (k0*3 + k1)*9 + k2*3 + o)*2 + par] = v;
    }
}

// ---------------------------------------------------------------------------
// K1: build cost volume (flat, fully parallel).
// ---------------------------------------------------------------------------
__global__ void k_build_cv(const float* __restrict__ x) {
    unsigned idx = blockIdx.x * blockDim.x + threadIdx.x;
    if (idx >= (unsigned)(BB*MCC*HWD)) return;
    unsigned i = idx;
    int d  = i % NDD;  i /= NDD;
    int w  = i % WW;   i /= WW;
    int h  = i % HH;   i /= HH;
    int mc = i % MCC;  i /= MCC;
    int b  = i;
    int m = mc / CCH, c = mc % CCH;
    int ws = w + (d - 4) * (m - 4);
    float v = 0.f;
    if ((unsigned)ws < WW)
        v = x[(((size_t)(b*CCH + c)*HH + h)*WW + ws)*MM + m];
    g_cv[idx] = v;
}

// ---------------------------------------------------------------------------
// K2: mean pool per (b,mc). Deterministic tree reduce.
// ---------------------------------------------------------------------------
__global__ void k_reduce() {
    int bm = blockIdx.x;
    const float* src = g_cv + (size_t)bm * HWD;
    float s = 0.f;
    for (int i = threadIdx.x; i < HWD; i += 256) s += src[i];
    __shared__ float sh[256];
    sh[threadIdx.x] = s;
    __syncthreads();
    for (int o = 128; o > 0; o >>= 1) {
        if (threadIdx.x < o) sh[threadIdx.x] += sh[threadIdx.x + o];
        __syncthreads();
    }
    if (threadIdx.x == 0) g_p[bm] = sh[0] * (1.0f / HWD);
}

// ---------------------------------------------------------------------------
// K3: global attention branch (center tap only at 1x1x1 spatial).
// ---------------------------------------------------------------------------
__global__ void k_global(const float* __restrict__ w1, const float* __restrict__ b1,
                         const float* __restrict__ g1, const float* __restrict__ be1,
                         const float* __restrict__ m1, const float* __restrict__ v1,
                         const float* __restrict__ w2, const float* __restrict__ b2,
                         const float* __restrict__ g2, const float* __restrict__ be2,
                         const float* __restrict__ m2, const float* __restrict__ v2) {
    __shared__ float gh[BB*HIDN];
    int t = threadIdx.x;
    if (t < BB*HIDN) {
        int b = t / HIDN, o = t % HIDN;
        float s = b1[o];
        for (int c = 0; c < MCC; c++)
            s += w1[(o*MCC + c)*27 + 13] * g_p[b*MCC + c];
        float sc = g1[o] * rsqrtf(v1[o] + EPSBN);
        s = (s - m1[o]) * sc + be1[o];
        gh[t] = fmaxf(s, 0.f);
    }
    __syncthreads();
    if (t < BB*MM) {
        int b = t / MM, og = t % MM;
        float s = b2[og];
        for (int o = 0; o < HIDN; o++)
            s += w2[(og*HIDN + o)*27 + 13] * gh[b*HIDN + o];
        float sc = g2[og] * rsqrtf(v2[og] + EPSBN);
        g_xg[t] = (s - m2[og]) * sc + be2[og];
    }
}

// ---------------------------------------------------------------------------
// K4/K5: 3x3x3 conv, f32x2 channel-pair, cp.async double-buffered pipeline.
// Thread: one (h,w), 3 oc, 9 d. Cell = 26 floats: z 0..10 x {c_even,c_odd}.
// Step = one channel-pair: 3240 data elems + 162 weight floats per buffer.
// Block 128 = 16(w) x 8(h). grid z = B*NOCG (3 oc per group).
// ---------------------------------------------------------------------------
#define NELEM 3240   // 180 cells * 2c * 9d
#define NITER 26     // ceil(3240/128)

template<int CPAIRS, int NOCG, int OCTOT, bool FIRST>
__global__ __launch_bounds__(128) void k_conv(
        const float* __restrict__ gam, const float* __restrict__ bet,
        const float* __restrict__ mu,  const float* __restrict__ var,
        const float* __restrict__ bias) {
    __shared__ __align__(16) float tile[2][180*26];
    __shared__ __align__(16) float wsh[2][162];

    const float* src = FIRST ? g_cv : g_h1;
    const float* wpk = FIRST ? g_w1p : g_w2p;
    float* dst       = FIRST ? g_h1 : g_wei;

    int tid = threadIdx.x;
    int tx = tid & 15, ty = tid >> 4;        // 16 x 8
    int gz = blockIdx.z;
    int b = gz / NOCG, g = gz % NOCG;
    int w0 = blockIdx.x * 16, h0 = blockIdx.y * 8;

    // zero both buffers (halo z-slots must stay 0; data slots rewritten each step)
    for (int i = tid; i < 2*180*26; i += 128) ((float*)tile)[i] = 0.f;
    __syncthreads();

    const float* srcb = src + (size_t)b*(2*CPAIRS)*HWD;
    const float* wg   = wpk + (size_t)g*CPAIRS*162;
    unsigned tile_u = (unsigned)__cvta_generic_to_shared(&tile[0][0]);
    unsigned wsh_u  = (unsigned)__cvta_generic_to_shared(&wsh[0][0]);

    // ---- async load of channel-pair `cp` into buffer `buf` ----
    auto issue = [&](int cpi, int buf) {
        const float* cb = srcb + (size_t)(2*cpi)*HWD;
        unsigned sbase = tile_u + buf*(180*26*4);
#pragma unroll
        for (int j = 0; j < NITER; j++) {
            int idx = j*128 + tid;
            bool pv = (idx < NELEM);
            int cell = idx / 18;  int rem = idx - cell*18;
            int c = rem / 9;      int d = rem - c*9;
            int hi = cell / 18;   int wi = cell - hi*18;
            int h = h0 - 1 + hi,  w = w0 - 1 + wi;
            bool val = pv && ((unsigned)h < HH) && ((unsigned)w < WW);
            const float* gp = val ? (cb + (size_t)c*HWD + (h*WW + w)*9 + d) : cb;
            if (pv) cpa4(sbase + (unsigned)(cell*26 + 2*(d+1) + c)*4, gp, val);
        }
        const float* wsrc = wg + (size_t)cpi*162;
        unsigned wbase = wsh_u + buf*(162*4);
#pragma unroll
        for (int j = 0; j < 2; j++) {
            int idx = j*128 + tid;
            if (idx < 162) cpa4(wbase + (unsigned)idx*4, wsrc + idx, true);
        }
        cpa_commit();
    };

    u64 acc[3][9];
#pragma unroll
    for (int o = 0; o < 3; o++)
#pragma unroll
        for (int d = 0; d < 9; d++) acc[o][d] = 0ull;

    issue(0, 0);
    if (CPAIRS > 1) issue(1, 1);

    for (int s = 0; s < CPAIRS; s++) {
        if (s + 1 < CPAIRS) asm volatile("cp.async.wait_group 1;");
        else                asm volatile("cp.async.wait_group 0;");
        __syncthreads();

        int cur = s & 1;
        const float* tb = tile[cur];
        const u64*   wb = (const u64*)wsh[cur];
#pragma unroll
        for (int k0 = 0; k0 < 3; k0++)
#pragma unroll
        for (int k1 = 0; k1 < 3; k1++) {
            const u64* xc = (const u64*)(tb + ((ty + k0)*18 + (tx + k1))*26);
            u64 X[11];
#pragma unroll
            for (int z = 0; z < 11; z++) X[z] = xc[z];
            const u64* wr = wb + (k0*3 + k1)*9;
#pragma unroll
            for (int k2 = 0; k2 < 3; k2++)
#pragma unroll
            for (int o = 0; o < 3; o++) {
                u64 wv = wr[k2*3 + o];
#pragma unroll
                for (int d = 0; d < 9; d++)
                    fma2(acc[o][d], wv, X[d + k2]);
            }
        }
        __syncthreads();
        if (s + 2 < CPAIRS) issue(s + 2, cur);
    }

    int h = h0 + ty, w = w0 + tx;
#pragma unroll
    for (int o = 0; o < 3; o++) {
        int oc = g*3 + o;
        float s  = gam[oc] * rsqrtf(var[oc] + EPSBN);
        float bi = (bias[oc] - mu[oc]) * s + bet[oc];
        float xg = FIRST ? 0.f : g_xg[b*MM + oc];
        float* dp = dst + (size_t)(b*OCTOT + oc)*HWD + (h*WW + w)*9;
#pragma unroll
        for (int d = 0; d < 9; d++) {
            float lo, hi;
            upk2(lo, hi, acc[o][d]);
            float y = (lo + hi)*s + bi;
            if (FIRST) y = fmaxf(y, 0.f);
            else       y = 1.f / (1.f + expf(-(y + xg)));
            dp[d] = y;
        }
    }
}

// ---------------------------------------------------------------------------
// K6: conv_last GEMM with f32x2.
// ---------------------------------------------------------------------------
extern __shared__ float sfin[];
__global__ __launch_bounds__(256) void k_final(
        const float* __restrict__ clw, const float* __restrict__ clb,
        float* __restrict__ out) {
    float* As = sfin;               // [144][128]
    float* Ws = sfin + 144*128;     // [144][162] (oc >= 150 zero)
    int b  = blockIdx.y;
    int p0 = blockIdx.x * 128;
    int tid = threadIdx.x;

    for (int t = tid; t < 162*144; t += 256) {
        int oc = t / 144, k = t % 144;
        Ws[k*162 + oc] = (oc < OUTC) ? clw[oc*MCC + k] : 0.f;
    }
    const float* cvb = g_cv  + (size_t)b*MCC*HWD + p0;
    const float* wb  = g_wei + (size_t)b*MM *HWD + p0;
    for (int t = tid; t < 144*128; t += 256) {
        int k = t >> 7, p = t & 127;
        As[t] = cvb[(size_t)k*HWD + p] * wb[(size_t)(k >> 4)*HWD + p];
    }
    __syncthreads();

    int tx = tid & 31, ty = tid >> 5;
    u64 acc[10][4];
#pragma unroll
    for (int j = 0; j < 10; j++)
#pragma unroll
        for (int i = 0; i < 4; i++) acc[j][i] = 0ull;

#pragma unroll 2
    for (int k = 0; k < 144; k++) {
        float4 a = *(const float4*)(As + k*128 + tx*4);
        u64 a0 = pk2(a.x, a.x), a1 = pk2(a.y, a.y);
        u64 a2 = pk2(a.z, a.z), a3 = pk2(a.w, a.w);
        const u64* wrow = (const u64*)(Ws + k*162) + ty*10;
#pragma unroll
        for (int j = 0; j < 10; j++) {
            u64 wv = wrow[j];
            fma2(acc[j][0], wv, a0); fma2(acc[j][1], wv, a1);
            fma2(acc[j][2], wv, a2); fma2(acc[j][3], wv, a3);
        }
    }

#pragma unroll
    for (int j = 0; j < 10; j++) {
        int oc0 = ty*20 + 2*j;
        float lo[4], hi[4];
#pragma unroll
        for (int i = 0; i < 4; i++) upk2(lo[i], hi[i], acc[j][i]);
        if (oc0 < OUTC) {
            float bv = clb[oc0];
            float4 r = make_float4(lo[0]+bv, lo[1]+bv, lo[2]+bv, lo[3]+bv);
            *(float4*)(out + (size_t)(b*OUTC + oc0)*HWD + p0 + tx*4) = r;
        }
        if (oc0 + 1 < OUTC) {
            float bv = clb[oc0+1];
            float4 r = make_float4(hi[0]+bv, hi[1]+bv, hi[2]+bv, hi[3]+bv);
            *(float4*)(out + (size_t)(b*OUTC + oc0 + 1)*HWD + p0 + tx*4) = r;
        }
    }
}

// ---------------------------------------------------------------------------
extern "C" void kernel_launch(void* const* d_in, const int* in_sizes, int n_in,
                              void* d_out, int out_size) {
    const float* x      = (const float*)d_in[0];
    const float* la_w1  = (const float*)d_in[1];
    const float* la_b1  = (const float*)d_in[2];
    const float* la_g1  = (const float*)d_in[3];
    const float* la_be1 = (const float*)d_in[4];
    const float* la_m1  = (const float*)d_in[5];
    const float* la_v1  = (const float*)d_in[6];
    const float* la_w2  = (const float*)d_in[7];
    const float* la_b2  = (const float*)d_in[8];
    const float* la_g2  = (const float*)d_in[9];
    const float* la_be2 = (const float*)d_in[10];
    const float* la_m2  = (const float*)d_in[11];
    const float* la_v2  = (const float*)d_in[12];
    const float* ga_w1  = (const float*)d_in[13];
    const float* ga_b1  = (const float*)d_in[14];
    const float* ga_g1  = (const float*)d_in[15];
    const float* ga_be1 = (const float*)d_in[16];
    const float* ga_m1  = (const float*)d_in[17];
    const float* ga_v1  = (const float*)d_in[18];
    const float* ga_w2  = (const float*)d_in[19];
    const float* ga_b2  = (const float*)d_in[20];
    const float* ga_g2  = (const float*)d_in[21];
    const float* ga_be2 = (const float*)d_in[22];
    const float* ga_m2  = (const float*)d_in[23];
    const float* ga_v2  = (const float*)d_in[24];
    const float* cl_w   = (const float*)d_in[25];
    const float* cl_b   = (const float*)d_in[26];
    float* out = (float*)d_out;

    // Launch order chosen so conv1 is launch index 3 (profiler captures idx 3).
    k_packw<<<(HIDN*MCC*27 + 255)/256, 256>>>(la_w1, la_w2);          // 0
    unsigned ncv = BB*MCC*HWD;
    k_build_cv<<<(ncv + 255)/256, 256>>>(x);                           // 1
    k_reduce<<<BB*MCC, 256>>>();                                       // 2

    dim3 g1(WW/16, HH/8, BB*6);
    k_conv<72, 6, 18, true><<<g1, 128>>>(la_g1, la_be1, la_m1, la_v1, la_b1);   // 3

    k_global<<<1, 64>>>(ga_w1, ga_b1, ga_g1, ga_be1, ga_m1, ga_v1,
                        ga_w2, ga_b2, ga_g2, ga_be2, ga_m2, ga_v2);    // 4

    dim3 g2(WW/16, HH/8, BB*3);
    k_conv<9, 3, 9, false><<<g2, 128>>>(la_g2, la_be2, la_m2, la_v2, la_b2);    // 5

    const int smem_fin = (144*128 + 144*162) * 4;   // 167040
    cudaFuncSetAttribute(k_final, cudaFuncAttributeMaxDynamicSharedMemorySize, smem_fin);
    dim3 gf(HWD/128, BB);
    k_final<<<gf, 256, smem_fin>>>(cl_w, cl_b, out);                   // 6
}

// round 7
// speedup vs baseline: 1.6097x; 1.0413x over previous
#include <cuda_runtime.h>
#include <math.h>

// Problem dims
#define BB   2
#define CCH  16
#define HH   128
#define WW   128
#define MM   9
#define NDD  9
#define MCC  144
#define HIDN 18
#define OUTC 150
#define HWD  (HH*WW*NDD)   // 147456
#define EPSBN 1e-5f

// Scratch (device globals; no runtime allocation allowed)
__device__ float g_cv [BB*(size_t)MCC*HWD];   // cost volume  [b][mc][h][w][d]
__device__ float g_h1 [BB*(size_t)HIDN*HWD];  // hidden
__device__ float g_wei[BB*(size_t)MM*HWD];    // sigmoid attention
__device__ float g_p  [BB*MCC];               // global mean pool
__device__ float g_xg [BB*MM];                // global-branch logits
// conv weights channel-pair packed: [g][cpair][(k0*3+k1)*9 + k2*3 + o] -> u64 {w_c0, w_c1}
__device__ float g_w1p[6*72*81*2];            // conv1: 6 ocg x 72 cpairs
__device__ float g_w2p[3*9*81*2];             // conv2: 3 ocg x 9 cpairs

typedef unsigned long long u64;

__device__ __forceinline__ void upk2(float &lo, float &hi, u64 v) {
    unsigned a, b;
    asm("mov.b64 {%0, %1}, %2;" : "=r"(a), "=r"(b) : "l"(v));
    lo = __uint_as_float(a); hi = __uint_as_float(b);
}
__device__ __forceinline__ void fma2(u64 &d, u64 a, u64 b) {
    asm("fma.rn.f32x2 %0, %1, %2, %0;" : "+l"(d) : "l"(a), "l"(b));
}
__device__ __forceinline__ u64 pk2(float lo, float hi) {
    u64 r;
    asm("mov.b64 %0, {%1, %2};" : "=l"(r) : "r"(__float_as_uint(lo)), "r"(__float_as_uint(hi)));
    return r;
}
__device__ __forceinline__ void cpa4(unsigned saddr, const void* gaddr, bool valid) {
    int sz = valid ? 4 : 0;   // src-size 0 -> zero-fill, no global read
    asm volatile("cp.async.ca.shared.global [%0], [%1], 4, %2;"
                 :: "r"(saddr), "l"(gaddr), "r"(sz));
}
__device__ __forceinline__ void cpa_commit() {
    asm volatile("cp.async.commit_group;");
}

// ---------------------------------------------------------------------------
// K-pack: channel-pair interleave conv weights.
// ---------------------------------------------------------------------------
__global__ void k_packw(const float* __restrict__ w1, const float* __restrict__ w2) {
    int t = blockIdx.x * 256 + threadIdx.x;
    if (t < HIDN*MCC*27) {
        int tap = t % 27; int r = t / 27;
        int ch = r % MCC; int oc = r / MCC;
        int k0 = tap / 9, k1 = (tap / 3) % 3, k2 = tap % 3;
        int g = oc / 3, o = oc % 3;
        int cp = ch >> 1, par = ch & 1;
        float v = w1[((size_t)oc*MCC + ch)*27 + tap];
        g_w1p[(((size_t)(g*72 + cp)*81) + (k0*3 + k1)*9 + k2*3 + o)*2 + par] = v;
    }
    if (t < MM*HIDN*27) {
        int tap = t % 27; int r = t / 27;
        int ch = r % HIDN; int oc = r / HIDN;
        int k0 = tap / 9, k1 = (tap / 3) % 3, k2 = tap % 3;
        int g = oc / 3, o = oc % 3;
        int cp = ch >> 1, par = ch & 1;
        float v = w2[((size_t)oc*HIDN + ch)*27 + tap];
        g_w2p[(((size_t)(g*9 + cp)*81) + (k0*3 + k1)*9 + k2*3 + o)*2 + par] = v;
    }
}

// ---------------------------------------------------------------------------
// K1: build cost volume (flat, fully parallel).
// ---------------------------------------------------------------------------
__global__ void k_build_cv(const float* __restrict__ x) {
    unsigned idx = blockIdx.x * blockDim.x + threadIdx.x;
    if (idx >= (unsigned)(BB*MCC*HWD)) return;
    unsigned i = idx;
    int d  = i % NDD;  i /= NDD;
    int w  = i % WW;   i /= WW;
    int h  = i % HH;   i /= HH;
    int mc = i % MCC;  i /= MCC;
    int b  = i;
    int m = mc / CCH, c = mc % CCH;
    int ws = w + (d - 4) * (m - 4);
    float v = 0.f;
    if ((unsigned)ws < WW)
        v = x[(((size_t)(b*CCH + c)*HH + h)*WW + ws)*MM + m];
    g_cv[idx] = v;
}

// ---------------------------------------------------------------------------
// K2: mean pool per (b,mc). Deterministic tree reduce.
// ---------------------------------------------------------------------------
__global__ void k_reduce() {
    int bm = blockIdx.x;
    const float* src = g_cv + (size_t)bm * HWD;
    float s = 0.f;
    for (int i = threadIdx.x; i < HWD; i += 256) s += src[i];
    __shared__ float sh[256];
    sh[threadIdx.x] = s;
    __syncthreads();
    for (int o = 128; o > 0; o >>= 1) {
        if (threadIdx.x < o) sh[threadIdx.x] += sh[threadIdx.x + o];
        __syncthreads();
    }
    if (threadIdx.x == 0) g_p[bm] = sh[0] * (1.0f / HWD);
}

// ---------------------------------------------------------------------------
// K3: global attention branch (center tap only at 1x1x1 spatial).
// ---------------------------------------------------------------------------
__global__ void k_global(const float* __restrict__ w1, const float* __restrict__ b1,
                         const float* __restrict__ g1, const float* __restrict__ be1,
                         const float* __restrict__ m1, const float* __restrict__ v1,
                         const float* __restrict__ w2, const float* __restrict__ b2,
                         const float* __restrict__ g2, const float* __restrict__ be2,
                         const float* __restrict__ m2, const float* __restrict__ v2) {
    __shared__ float gh[BB*HIDN];
    int t = threadIdx.x;
    if (t < BB*HIDN) {
        int b = t / HIDN, o = t % HIDN;
        float s = b1[o];
        for (int c = 0; c < MCC; c++)
            s += w1[(o*MCC + c)*27 + 13] * g_p[b*MCC + c];
        float sc = g1[o] * rsqrtf(v1[o] + EPSBN);
        s = (s - m1[o]) * sc + be1[o];
        gh[t] = fmaxf(s, 0.f);
    }
    __syncthreads();
    if (t < BB*MM) {
        int b = t / MM, og = t % MM;
        float s = b2[og];
        for (int o = 0; o < HIDN; o++)
            s += w2[(og*HIDN + o)*27 + 13] * gh[b*HIDN + o];
        float sc = g2[og] * rsqrtf(v2[og] + EPSBN);
        g_xg[t] = (s - m2[og]) * sc + be2[og];
    }
}

// ---------------------------------------------------------------------------
// K4/K5: 3x3x3 conv, f32x2 channel-pair, cp.async double-buffered pipeline.
// Cell-major load mapping: each thread owns <=2 cells, (h,w,valid) computed
// once per cell, 18 cp.async with constant offsets -> tiny register footprint.
// Cell = 26 floats: z 0..10 x {c_even,c_odd}; data z=1..9; halo z stays zero.
// Block 128 = 16(w) x 8(h). grid z = B*NOCG (3 oc per group).
// ---------------------------------------------------------------------------
template<int CPAIRS, int NOCG, int OCTOT, bool FIRST>
__global__ __launch_bounds__(128, 4) void k_conv(
        const float* __restrict__ gam, const float* __restrict__ bet,
        const float* __restrict__ mu,  const float* __restrict__ var,
        const float* __restrict__ bias) {
    __shared__ __align__(16) float tile[2][180*26];
    __shared__ __align__(16) float wsh[2][162];

    const float* src = FIRST ? g_cv : g_h1;
    const float* wpk = FIRST ? g_w1p : g_w2p;
    float* dst       = FIRST ? g_h1 : g_wei;

    int tid = threadIdx.x;
    int tx = tid & 15, ty = tid >> 4;        // 16 x 8
    int gz = blockIdx.z;
    int b = gz / NOCG, g = gz % NOCG;
    int w0 = blockIdx.x * 16, h0 = blockIdx.y * 8;

    // zero both buffers once (halo z slots 0 and 10 + pads must stay zero)
    for (int i = tid; i < 2*180*26; i += 128) ((float*)tile)[i] = 0.f;
    __syncthreads();

    const float* srcb = src + (size_t)b*(2*CPAIRS)*HWD;
    const float* wg   = wpk + (size_t)g*CPAIRS*162;
    unsigned tile_u = (unsigned)__cvta_generic_to_shared(&tile[0][0]);
    unsigned wsh_u  = (unsigned)__cvta_generic_to_shared(&wsh[0][0]);

    // Precompute per-thread cell geometry (constant across pipeline steps).
    // cell0 = tid, cell1 = tid + 128 (if < 180).
    int hi0 = tid / 18,        wi0 = tid % 18;
    int c1i = tid + 128;
    int hi1 = c1i / 18,        wi1 = c1i % 18;
    int h0a = h0 - 1 + hi0,    w0a = w0 - 1 + wi0;
    int h1a = h0 - 1 + hi1,    w1a = w0 - 1 + wi1;
    bool v0 = ((unsigned)h0a < HH) && ((unsigned)w0a < WW);
    bool v1 = (c1i < 180) && ((unsigned)h1a < HH) && ((unsigned)w1a < WW);
    bool has1 = (c1i < 180);
    size_t go0 = v0 ? (size_t)(h0a*WW + w0a)*9 : 0;
    size_t go1 = v1 ? (size_t)(h1a*WW + w1a)*9 : 0;
    unsigned so0 = (unsigned)(tid  * 26) * 4;
    unsigned so1 = (unsigned)(c1i * 26) * 4;

    auto issue = [&](int cpi, int buf) {
        const float* cb = srcb + (size_t)(2*cpi)*HWD;
        unsigned sbase = tile_u + buf*(180*26*4);
        const float* gp0 = cb + go0;
        const float* gp1 = cb + go1;
#pragma unroll
        for (int c = 0; c < 2; c++)
#pragma unroll
        for (int d = 0; d < 9; d++)
            cpa4(sbase + so0 + (unsigned)(2*(d+1)+c)*4, gp0 + (size_t)c*HWD + d, v0);
        if (has1) {
#pragma unroll
            for (int c = 0; c < 2; c++)
#pragma unroll
            for (int d = 0; d < 9; d++)
                cpa4(sbase + so1 + (unsigned)(2*(d+1)+c)*4, gp1 + (size_t)c*HWD + d, v1);
        }
        const float* wsrc = wg + (size_t)cpi*162;
        unsigned wbase = wsh_u + buf*(162*4);
        if (tid < 81) {   // 81 threads x 8B
            cpa4(wbase + (unsigned)tid*8,     wsrc + 2*tid,     true);
            cpa4(wbase + (unsigned)tid*8 + 4, wsrc + 2*tid + 1, true);
        }
        cpa_commit();
    };

    u64 acc[3][9];
#pragma unroll
    for (int o = 0; o < 3; o++)
#pragma unroll
        for (int d = 0; d < 9; d++) acc[o][d] = 0ull;

    issue(0, 0);
    if (CPAIRS > 1) issue(1, 1);

    for (int s = 0; s < CPAIRS; s++) {
        if (s + 1 < CPAIRS) asm volatile("cp.async.wait_group 1;");
        else                asm volatile("cp.async.wait_group 0;");
        __syncthreads();

        int cur = s & 1;
        const float* tb = tile[cur];
        const u64*   wb = (const u64*)wsh[cur];
#pragma unroll
        for (int k0 = 0; k0 < 3; k0++)
#pragma unroll
        for (int k1 = 0; k1 < 3; k1++) {
            const u64* xc = (const u64*)(tb + ((ty + k0)*18 + (tx + k1))*26);
            u64 X[11];
#pragma unroll
            for (int z = 0; z < 11; z++) X[z] = xc[z];
            const u64* wr = wb + (k0*3 + k1)*9;
#pragma unroll
            for (int k2 = 0; k2 < 3; k2++)
#pragma unroll
            for (int o = 0; o < 3; o++) {
                u64 wv = wr[k2*3 + o];
#pragma unroll
                for (int d = 0; d < 9; d++)
                    fma2(acc[o][d], wv, X[d + k2]);
            }
        }
        __syncthreads();
        if (s + 2 < CPAIRS) issue(s + 2, cur);
    }

    int h = h0 + ty, w = w0 + tx;
#pragma unroll
    for (int o = 0; o < 3; o++) {
        int oc = g*3 + o;
        float s  = gam[oc] * rsqrtf(var[oc] + EPSBN);
        float bi = (bias[oc] - mu[oc]) * s + bet[oc];
        float xg = FIRST ? 0.f : g_xg[b*MM + oc];
        float* dp = dst + (size_t)(b*OCTOT + oc)*HWD + (h*WW + w)*9;
#pragma unroll
        for (int d = 0; d < 9; d++) {
            float lo, hi;
            upk2(lo, hi, acc[o][d]);
            float y = (lo + hi)*s + bi;
            if (FIRST) y = fmaxf(y, 0.f);
            else       y = 1.f / (1.f + expf(-(y + xg)));
            dp[d] = y;
        }
    }
}

// ---------------------------------------------------------------------------
// K6: conv_last GEMM with f32x2.
// ---------------------------------------------------------------------------
extern __shared__ float sfin[];
__global__ __launch_bounds__(256) void k_final(
        const float* __restrict__ clw, const float* __restrict__ clb,
        float* __restrict__ out) {
    float* As = sfin;               // [144][128]
    float* Ws = sfin + 144*128;     // [144][162] (oc >= 150 zero)
    int b  = blockIdx.y;
    int p0 = blockIdx.x * 128;
    int tid = threadIdx.x;

    for (int t = tid; t < 162*144; t += 256) {
        int oc = t / 144, k = t % 144;
        Ws[k*162 + oc] = (oc < OUTC) ? clw[oc*MCC + k] : 0.f;
    }
    const float* cvb = g_cv  + (size_t)b*MCC*HWD + p0;
    const float* wb  = g_wei + (size_t)b*MM *HWD + p0;
    for (int t = tid; t < 144*128; t += 256) {
        int k = t >> 7, p = t & 127;
        As[t] = cvb[(size_t)k*HWD + p] * wb[(size_t)(k >> 4)*HWD + p];
    }
    __syncthreads();

    int tx = tid & 31, ty = tid >> 5;
    u64 acc[10][4];
#pragma unroll
    for (int j = 0; j < 10; j++)
#pragma unroll
        for (int i = 0; i < 4; i++) acc[j][i] = 0ull;

#pragma unroll 2
    for (int k = 0; k < 144; k++) {
        float4 a = *(const float4*)(As + k*128 + tx*4);
        u64 a0 = pk2(a.x, a.x), a1 = pk2(a.y, a.y);
        u64 a2 = pk2(a.z, a.z), a3 = pk2(a.w, a.w);
        const u64* wrow = (const u64*)(Ws + k*162) + ty*10;
#pragma unroll
        for (int j = 0; j < 10; j++) {
            u64 wv = wrow[j];
            fma2(acc[j][0], wv, a0); fma2(acc[j][1], wv, a1);
            fma2(acc[j][2], wv, a2); fma2(acc[j][3], wv, a3);
        }
    }

#pragma unroll
    for (int j = 0; j < 10; j++) {
        int oc0 = ty*20 + 2*j;
        float lo[4], hi[4];
#pragma unroll
        for (int i = 0; i < 4; i++) upk2(lo[i], hi[i], acc[j][i]);
        if (oc0 < OUTC) {
            float bv = clb[oc0];
            float4 r = make_float4(lo[0]+bv, lo[1]+bv, lo[2]+bv, lo[3]+bv);
            *(float4*)(out + (size_t)(b*OUTC + oc0)*HWD + p0 + tx*4) = r;
        }
        if (oc0 + 1 < OUTC) {
            float bv = clb[oc0+1];
            float4 r = make_float4(hi[0]+bv, hi[1]+bv, hi[2]+bv, hi[3]+bv);
            *(float4*)(out + (size_t)(b*OUTC + oc0 + 1)*HWD + p0 + tx*4) = r;
        }
    }
}

// ---------------------------------------------------------------------------
extern "C" void kernel_launch(void* const* d_in, const int* in_sizes, int n_in,
                              void* d_out, int out_size) {
    const float* x      = (const float*)d_in[0];
    const float* la_w1  = (const float*)d_in[1];
    const float* la_b1  = (const float*)d_in[2];
    const float* la_g1  = (const float*)d_in[3];
    const float* la_be1 = (const float*)d_in[4];
    const float* la_m1  = (const float*)d_in[5];
    const float* la_v1  = (const float*)d_in[6];
    const float* la_w2  = (const float*)d_in[7];
    const float* la_b2  = (const float*)d_in[8];
    const float* la_g2  = (const float*)d_in[9];
    const float* la_be2 = (const float*)d_in[10];
    const float* la_m2  = (const float*)d_in[11];
    const float* la_v2  = (const float*)d_in[12];
    const float* ga_w1  = (const float*)d_in[13];
    const float* ga_b1  = (const float*)d_in[14];
    const float* ga_g1  = (const float*)d_in[15];
    const float* ga_be1 = (const float*)d_in[16];
    const float* ga_m1  = (const float*)d_in[17];
    const float* ga_v1  = (const float*)d_in[18];
    const float* ga_w2  = (const float*)d_in[19];
    const float* ga_b2  = (const float*)d_in[20];
    const float* ga_g2  = (const float*)d_in[21];
    const float* ga_be2 = (const float*)d_in[22];
    const float* ga_m2  = (const float*)d_in[23];
    const float* ga_v2  = (const float*)d_in[24];
    const float* cl_w   = (const float*)d_in[25];
    const float* cl_b   = (const float*)d_in[26];
    float* out = (float*)d_out;

    // Launch order: conv1 at index 3 (profiler captures idx 3).
    k_packw<<<(HIDN*MCC*27 + 255)/256, 256>>>(la_w1, la_w2);          // 0
    unsigned ncv = BB*MCC*HWD;
    k_build_cv<<<(ncv + 255)/256, 256>>>(x);                           // 1
    k_reduce<<<BB*MCC, 256>>>();                                       // 2

    dim3 g1(WW/16, HH/8, BB*6);
    k_conv<72, 6, 18, true><<<g1, 128>>>(la_g1, la_be1, la_m1, la_v1, la_b1);   // 3

    k_global<<<1, 64>>>(ga_w1, ga_b1, ga_g1, ga_be1, ga_m1, ga_v1,
                        ga_w2, ga_b2, ga_g2, ga_be2, ga_m2, ga_v2);    // 4

    dim3 g2(WW/16, HH/8, BB*3);
    k_conv<9, 3, 9, false><<<g2, 128>>>(la_g2, la_be2, la_m2, la_v2, la_b2);    // 5

    const int smem_fin = (144*128 + 144*162) * 4;   // 167040
    cudaFuncSetAttribute(k_final, cudaFuncAttributeMaxDynamicSharedMemorySize, smem_fin);
    dim3 gf(HWD/128, BB);
    k_final<<<gf, 256, smem_fin>>>(cl_w, cl_b, out);                   // 6
}